// round 6
// baseline (speedup 1.0000x reference)
#include <cuda_runtime.h>

// Problem constants
#define TT    1200              // time length
#define NF    10                // conv filters
#define KK    17                // conv kernel width (pad 8 both sides)
#define WSTR  18                // padded per-filter weight stride (u64), 16B-aligned
#define NSTR  240               // 5-wide output strips per row (1200/5)
#define NTP   76                // pooled length
#define NTPG  19                // groups of 4 pooled outputs (76/4)
#define FEAT  (NF*NTP)          // 760
#define ROWS  2                 // (b,m) rows per block (the f32x2 SIMD pair)
#define THREADS 256

typedef unsigned long long u64;

__device__ __forceinline__ u64 pack2(float lo, float hi) {
    u64 r;
    asm("mov.b64 %0, {%1, %2};" : "=l"(r) : "f"(lo), "f"(hi));
    return r;
}
__device__ __forceinline__ void unpack2(u64 v, float& lo, float& hi) {
    asm("mov.b64 {%0, %1}, %2;" : "=f"(lo), "=f"(hi) : "l"(v));
}
__device__ __forceinline__ u64 ffma2(u64 a, u64 b, u64 c) {
    u64 d;
    asm("fma.rn.f32x2 %0, %1, %2, %3;" : "=l"(d) : "l"(a), "l"(b), "l"(c));
    return d;
}
__device__ __forceinline__ u64 add2(u64 a, u64 b) {
    u64 d;
    asm("add.rn.f32x2 %0, %1, %2;" : "=l"(d) : "l"(a), "l"(b));
    return d;
}
__device__ __forceinline__ u64 sub2(u64 a, u64 b) {
    u64 d;
    asm("sub.rn.f32x2 %0, %1, %2;" : "=l"(d) : "l"(a), "l"(b));
    return d;
}

__global__ __launch_bounds__(THREADS, 2) void scorer_kernel(
    const float* __restrict__ x,       // (B,1,M,T) rows of 1200
    const float* __restrict__ conv_w,  // (NF,1,KK)
    const float* __restrict__ conv_b,  // (NF)
    const float* __restrict__ lin_w,   // (M, FEAT)
    const float* __restrict__ lin_b,   // (M)
    float* __restrict__ out)           // (B,M,1)
{
    __shared__ u64 s_x2[TT + 16];                  // {row0,row1} pairs, 8-zero halo each side
    __shared__ __align__(16) u64 s_w2[NF * WSTR];  // {w,w}, padded stride 18 (16B/filter aligned)
    __shared__ u64   s_b2[NF];                     // {b,b}
    __shared__ u64   s_S2[NF * NSTR];              // packed {S_row0, S_row1} strip sums
    __shared__ float s_out[ROWS];

    const int tid  = threadIdx.x;
    const int row0 = blockIdx.x * ROWS;    // row = b*64 + m
    const int m0   = row0 & 63;

    // ---- Phase 0: stage packed padded weights, halos, interleaved x rows ----
    for (int i = tid; i < NF * WSTR; i += THREADS) {
        int f = i / WSTR, k = i - f * WSTR;
        float w = (k < KK) ? conv_w[f * KK + k] : 0.f;
        s_w2[i] = pack2(w, w);
    }
    if (tid < NF)   { float b = conv_b[tid]; s_b2[tid] = pack2(b, b); }
    if (tid < ROWS) s_out[tid] = 0.f;
    if (tid >= THREADS - 16) {
        int j = tid - (THREADS - 16);
        if (j < 8) s_x2[j] = 0ull;             // left halo
        else       s_x2[TT + j] = 0ull;        // right halo
    }
    {
        const float* xr0 = x + (size_t)row0 * TT;
        const float* xr1 = xr0 + TT;
        for (int t = tid; t < TT; t += THREADS)
            s_x2[8 + t] = pack2(xr0[t], xr1[t]);   // coalesced within each row
    }
    __syncthreads();

    // ---- Phase 1: per 5-output strip, ALL filters: conv -> +b -> square -> strip sum ----
    if (tid < NSTR) {
        const int s = tid;
        const u64* xp = &s_x2[5 * s];          // window x[5s-8 .. 5s+12]
        u64 xv[21];
        #pragma unroll
        for (int j = 0; j < 21; ++j) xv[j] = xp[j];

        for (int f = 0; f < NF; ++f) {
            const ulonglong2* wv = (const ulonglong2*)&s_w2[f * WSTR];

            // Load the whole filter into registers: 9 batched LDS.128 (MLP), one wait.
            ulonglong2 wr[8];
            #pragma unroll
            for (int kp = 0; kp < 8; ++kp) wr[kp] = wv[kp];
            const u64 w16 = ((const u64*)wv)[16];

            const u64 b2 = s_b2[f];
            u64 c0 = b2, c1 = b2, c2 = b2, c3 = b2, c4 = b2;

            // Pure FFMA2 burst: 90 ops, 5 independent chains -> pipe-saturating ILP.
            #pragma unroll
            for (int kp = 0; kp < 8; ++kp) {
                const int k = 2 * kp;
                c0 = ffma2(xv[k    ], wr[kp].x, c0);
                c1 = ffma2(xv[k + 1], wr[kp].x, c1);
                c2 = ffma2(xv[k + 2], wr[kp].x, c2);
                c3 = ffma2(xv[k + 3], wr[kp].x, c3);
                c4 = ffma2(xv[k + 4], wr[kp].x, c4);
                c0 = ffma2(xv[k + 1], wr[kp].y, c0);
                c1 = ffma2(xv[k + 2], wr[kp].y, c1);
                c2 = ffma2(xv[k + 3], wr[kp].y, c2);
                c3 = ffma2(xv[k + 4], wr[kp].y, c3);
                c4 = ffma2(xv[k + 5], wr[kp].y, c4);
            }
            c0 = ffma2(xv[16], w16, c0);
            c1 = ffma2(xv[17], w16, c1);
            c2 = ffma2(xv[18], w16, c2);
            c3 = ffma2(xv[19], w16, c3);
            c4 = ffma2(xv[20], w16, c4);

            u64 S = ffma2(c0, c0, 0ull);       // {0,0} == {0.f,0.f}
            S = ffma2(c1, c1, S);
            S = ffma2(c2, c2, S);
            S = ffma2(c3, c3, S);
            S = ffma2(c4, c4, S);
            s_S2[f * NSTR + s] = S;            // one STS.64, both rows
        }
    }
    __syncthreads();

    // ---- Phase 2: packed sliding pool (15 strips / window, hop 3) -> log -> dot ----
    float part0 = 0.f, part1 = 0.f;
    for (int task = tid; task < NF * NTPG; task += THREADS) {   // 190 tasks
        int f = task / NTPG;
        int g = task - f * NTPG;               // covers tp = 4g .. 4g+3

        const u64* Sp = &s_S2[f * NSTR + 12 * g];
        u64 run2 = Sp[0];
        #pragma unroll
        for (int j = 1; j < 15; ++j) run2 = add2(run2, Sp[j]);

        const size_t fb = (size_t)f * NTP + 4 * g;
        const float4 lw0 = *(const float4*)&lin_w[(size_t)m0 * FEAT + fb];
        const float4 lw1 = *(const float4*)&lin_w[(size_t)(m0 + 1) * FEAT + fb];

        #pragma unroll
        for (int q = 0; q < 4; ++q) {
            float p0, p1; unpack2(run2, p0, p1);
            p0 = fmaxf(p0 * (1.0f / 75.0f), 1e-10f);
            p1 = fmaxf(p1 * (1.0f / 75.0f), 1e-10f);
            const float v0 = __logf(p0);
            const float v1 = __logf(p1);
            const float w0 = (q == 0) ? lw0.x : (q == 1) ? lw0.y : (q == 2) ? lw0.z : lw0.w;
            const float w1 = (q == 0) ? lw1.x : (q == 1) ? lw1.y : (q == 2) ? lw1.z : lw1.w;
            part0 = fmaf(v0, w0, part0);
            part1 = fmaf(v1, w1, part1);
            if (q < 3) {
                u64 addv = add2(add2(Sp[15 + 3*q], Sp[16 + 3*q]), Sp[17 + 3*q]);
                u64 subv = add2(add2(Sp[3*q], Sp[1 + 3*q]), Sp[2 + 3*q]);
                run2 = sub2(add2(run2, addv), subv);
            }
        }
    }
    #pragma unroll
    for (int off = 16; off > 0; off >>= 1) {
        part0 += __shfl_down_sync(0xffffffffu, part0, off);
        part1 += __shfl_down_sync(0xffffffffu, part1, off);
    }
    if ((tid & 31) == 0) {
        atomicAdd(&s_out[0], part0);
        atomicAdd(&s_out[1], part1);
    }
    __syncthreads();

    if (tid < ROWS) out[row0 + tid] = s_out[tid] + lin_b[m0 + tid];
}

extern "C" void kernel_launch(void* const* d_in, const int* in_sizes, int n_in,
                              void* d_out, int out_size) {
    const float* x      = (const float*)d_in[0];
    const float* conv_w = (const float*)d_in[1];
    const float* conv_b = (const float*)d_in[2];
    const float* lin_w  = (const float*)d_in[3];
    const float* lin_b  = (const float*)d_in[4];
    float* out = (float*)d_out;

    const int n_rows = 256 * 64;               // B*M
    scorer_kernel<<<n_rows / ROWS, THREADS>>>(x, conv_w, conv_b, lin_w, lin_b, out);
}

// round 7
// speedup vs baseline: 1.2018x; 1.2018x over previous
#include <cuda_runtime.h>

// Problem constants
#define TT    1200              // time length
#define NF    10                // conv filters
#define KK    17                // conv kernel width (pad 8 both sides)
#define WSTR  18                // padded per-filter weight stride (u64), 16B-aligned
#define NSTR  240               // 5-wide output strips per row (1200/5)
#define NTP   76                // pooled length
#define NTPG  19                // groups of 4 pooled outputs (76/4)
#define FEAT  (NF*NTP)          // 760
#define ROWS  2                 // (b,m) rows per block (the f32x2 SIMD pair)
#define THREADS 256

typedef unsigned long long u64;

__device__ __forceinline__ u64 pack2(float lo, float hi) {
    u64 r;
    asm("mov.b64 %0, {%1, %2};" : "=l"(r) : "f"(lo), "f"(hi));
    return r;
}
__device__ __forceinline__ void unpack2(u64 v, float& lo, float& hi) {
    asm("mov.b64 {%0, %1}, %2;" : "=f"(lo), "=f"(hi) : "l"(v));
}
__device__ __forceinline__ u64 ffma2(u64 a, u64 b, u64 c) {
    u64 d;
    asm("fma.rn.f32x2 %0, %1, %2, %3;" : "=l"(d) : "l"(a), "l"(b), "l"(c));
    return d;
}

__global__ __launch_bounds__(THREADS, 3) void scorer_kernel(
    const float* __restrict__ x,       // (B,1,M,T) rows of 1200
    const float* __restrict__ conv_w,  // (NF,1,KK)
    const float* __restrict__ conv_b,  // (NF)
    const float* __restrict__ lin_w,   // (M, FEAT)
    const float* __restrict__ lin_b,   // (M)
    float* __restrict__ out)           // (B,M,1)
{
    __shared__ u64 s_x2[TT + 16];                  // {row0,row1} pairs, 8-zero halo each side
    __shared__ __align__(16) u64 s_w2[NF * WSTR];  // {w,w}, padded stride 18 (16B/filter aligned)
    __shared__ u64   s_b2[NF];                     // {b,b}
    __shared__ float s_S[ROWS][NF * NSTR];         // 5-strip sums of conv^2
    __shared__ float s_out[ROWS];

    const int tid  = threadIdx.x;
    const int row0 = blockIdx.x * ROWS;    // row = b*64 + m
    const int m0   = row0 & 63;

    // ---- Phase 0: stage packed padded weights, halos, interleaved x rows ----
    for (int i = tid; i < NF * WSTR; i += THREADS) {
        int f = i / WSTR, k = i - f * WSTR;
        float w = (k < KK) ? conv_w[f * KK + k] : 0.f;
        s_w2[i] = pack2(w, w);
    }
    if (tid < NF)   { float b = conv_b[tid]; s_b2[tid] = pack2(b, b); }
    if (tid < ROWS) s_out[tid] = 0.f;
    if (tid >= THREADS - 16) {
        int j = tid - (THREADS - 16);
        if (j < 8) s_x2[j] = 0ull;             // left halo
        else       s_x2[TT + j] = 0ull;        // right halo
    }
    {
        const float* xr0 = x + (size_t)row0 * TT;
        const float* xr1 = xr0 + TT;
        for (int t = tid; t < TT; t += THREADS)
            s_x2[8 + t] = pack2(xr0[t], xr1[t]);   // coalesced within each row
    }
    __syncthreads();

    // ---- Phase 1: per 5-output strip, ALL filters: conv -> +b -> square -> strip sum ----
    if (tid < NSTR) {
        const int s = tid;
        const u64* xp = &s_x2[5 * s];          // window x[5s-8 .. 5s+12]
        u64 xv[21];
        #pragma unroll
        for (int j = 0; j < 21; ++j) xv[j] = xp[j];

        for (int f = 0; f < NF; ++f) {
            const ulonglong2* wv = (const ulonglong2*)&s_w2[f * WSTR];  // 16B-aligned
            const u64 b2 = s_b2[f];
            u64 c0 = b2, c1 = b2, c2 = b2, c3 = b2, c4 = b2;
            #pragma unroll
            for (int kp = 0; kp < 8; ++kp) {   // k = 2kp, 2kp+1
                const ulonglong2 wpair = wv[kp];   // one LDS.128 -> two weights, 10 FFMA2
                const int k = 2 * kp;
                c0 = ffma2(xv[k    ], wpair.x, c0);
                c1 = ffma2(xv[k + 1], wpair.x, c1);
                c2 = ffma2(xv[k + 2], wpair.x, c2);
                c3 = ffma2(xv[k + 3], wpair.x, c3);
                c4 = ffma2(xv[k + 4], wpair.x, c4);
                c0 = ffma2(xv[k + 1], wpair.y, c0);
                c1 = ffma2(xv[k + 2], wpair.y, c1);
                c2 = ffma2(xv[k + 3], wpair.y, c2);
                c3 = ffma2(xv[k + 4], wpair.y, c3);
                c4 = ffma2(xv[k + 5], wpair.y, c4);
            }
            {
                const u64 w16 = ((const u64*)wv)[16];  // k = 16
                c0 = ffma2(xv[16], w16, c0);
                c1 = ffma2(xv[17], w16, c1);
                c2 = ffma2(xv[18], w16, c2);
                c3 = ffma2(xv[19], w16, c3);
                c4 = ffma2(xv[20], w16, c4);
            }
            u64 S = ffma2(c0, c0, 0ull);       // {0,0} == {0.f,0.f}
            S = ffma2(c1, c1, S);
            S = ffma2(c2, c2, S);
            S = ffma2(c3, c3, S);
            S = ffma2(c4, c4, S);
            float S0, S1; unpack2(S, S0, S1);
            s_S[0][f * NSTR + s] = S0;
            s_S[1][f * NSTR + s] = S1;
        }
    }
    __syncthreads();

    // ---- Phase 2: sliding pool (15 strips per window, hop 3) -> log -> dot ----
    float part0 = 0.f, part1 = 0.f;
    for (int task = tid; task < ROWS * NF * NTPG; task += THREADS) {   // 380 tasks
        int r   = task / (NF * NTPG);
        int rem = task - r * (NF * NTPG);
        int f   = rem / NTPG;
        int g   = rem - f * NTPG;              // covers tp = 4g .. 4g+3

        const float* Sp = &s_S[r][f * NSTR + 12 * g];
        float sv[24];
        #pragma unroll
        for (int j = 0; j < 24; ++j) sv[j] = Sp[j];

        float run = 0.f;
        #pragma unroll
        for (int j = 0; j < 15; ++j) run += sv[j];

        const float4 lw = *(const float4*)&lin_w[(size_t)(m0 + r) * FEAT + f * NTP + 4 * g];
        float acc = 0.f;
        #pragma unroll
        for (int q = 0; q < 4; ++q) {
            float p = fmaxf(run * (1.0f / 75.0f), 1e-10f);
            float v = __logf(p);
            float w = (q == 0) ? lw.x : (q == 1) ? lw.y : (q == 2) ? lw.z : lw.w;
            acc = fmaf(v, w, acc);
            if (q < 3) {
                run += (sv[15 + 3*q] + sv[16 + 3*q] + sv[17 + 3*q])
                     - (sv[3*q] + sv[1 + 3*q] + sv[2 + 3*q]);
            }
        }
        if (r == 0) part0 += acc; else part1 += acc;
    }
    #pragma unroll
    for (int off = 16; off > 0; off >>= 1) {
        part0 += __shfl_down_sync(0xffffffffu, part0, off);
        part1 += __shfl_down_sync(0xffffffffu, part1, off);
    }
    if ((tid & 31) == 0) {
        atomicAdd(&s_out[0], part0);
        atomicAdd(&s_out[1], part1);
    }
    __syncthreads();

    if (tid < ROWS) out[row0 + tid] = s_out[tid] + lin_b[m0 + tid];
}

extern "C" void kernel_launch(void* const* d_in, const int* in_sizes, int n_in,
                              void* d_out, int out_size) {
    const float* x      = (const float*)d_in[0];
    const float* conv_w = (const float*)d_in[1];
    const float* conv_b = (const float*)d_in[2];
    const float* lin_w  = (const float*)d_in[3];
    const float* lin_b  = (const float*)d_in[4];
    float* out = (float*)d_out;

    const int n_rows = 256 * 64;               // B*M
    scorer_kernel<<<n_rows / ROWS, THREADS>>>(x, conv_w, conv_b, lin_w, lin_b, out);
}